// round 11
// baseline (speedup 1.0000x reference)
#include <cuda_runtime.h>
#include <cstdint>
#include <cstddef>

#define NB   1024
#define NC   8
#define NT   32
#define NE   128
#define NH   256
#define SEG  64
#define SIG  1056
#define THREADS 512

// ---------------- device scratch (static; no allocations) ----------------
__device__ __align__(16) float g_W1p[8 * 16 * 32 * 8];     // 32768 tf32, GEMM1-B frag pack
__device__ __align__(16) float g_W2T[NH * SEG];            // [h][s] = (Winv@W2)^T
__device__ __align__(16) float g_W2p[4 * 8 * 2 * 32 * 8];  // 16384 tf32, GEMM2-B frag pack (K4)
__device__ __align__(16) float g_b2i[SEG];                 // binv + Winv@b2

// ---------------- helpers ----------------
__device__ __forceinline__ uint32_t f2tf32(float x) {
    uint32_t u;
    asm("cvt.rna.tf32.f32 %0, %1;" : "=r"(u) : "f"(x));
    return u;
}
__device__ __forceinline__ void cpasync16(uint32_t saddr, const void* gaddr) {
    asm volatile("cp.async.cg.shared.global [%0], [%1], 16;" :: "r"(saddr), "l"(gaddr));
}
#define CPASYNC_COMMIT() asm volatile("cp.async.commit_group;")
#define CPASYNC_WAIT0()  asm volatile("cp.async.wait_group 0;")
#define BARS(id, cnt) asm volatile("bar.sync %0, %1;"   :: "r"(id), "r"(cnt) : "memory")
#define BARA(id, cnt) asm volatile("bar.arrive %0, %1;" :: "r"(id), "r"(cnt) : "memory")
#define MEMBAR_CTA()  asm volatile("membar.cta;" ::: "memory")

#define MMA_TF32(C, A, b0v, b1v)                                               \
    asm volatile(                                                              \
        "mma.sync.aligned.m16n8k8.row.col.f32.tf32.tf32.f32 "                  \
        "{%0,%1,%2,%3},{%4,%5,%6,%7},{%8,%9},{%0,%1,%2,%3};"                   \
        : "+f"((C)[0]), "+f"((C)[1]), "+f"((C)[2]), "+f"((C)[3])               \
        : "r"((A)[0]), "r"((A)[1]), "r"((A)[2]), "r"((A)[3]),                  \
          "r"(b0v), "r"(b1v))

// ---------------- prep kernels (identical to round 8) ----------------
__global__ void prep_w1p(const float* __restrict__ W1) {
    int id = blockIdx.x * 256 + threadIdx.x;     // 32768
    int v  = id & 7;
    int l  = (id >> 3) & 31;
    int ks = (id >> 8) & 15;
    int w  = id >> 12;
    int g = l >> 2, tg = l & 3, nt = v >> 1, hh = v & 1;
    int j = 32 * w + 8 * nt + g;
    int k = 8 * ks + tg + 4 * hh;
    ((uint32_t*)g_W1p)[id] = f2tf32(W1[j * NE + k]);
}

__global__ void prep_w2(const float* __restrict__ W2, const float* __restrict__ Winv,
                        const float* __restrict__ b2, const float* __restrict__ binv) {
    int s = blockIdx.x;        // 64
    int h = threadIdx.x;       // 256
    const float* wr = Winv + s * NE;
    float acc = 0.f;
    #pragma unroll 4
    for (int e = 0; e < NE; ++e) acc += wr[e] * W2[e * NH + h];
    g_W2T[h * SEG + s] = acc;
    if (h == 0) {
        float t = 0.f;
        for (int e = 0; e < NE; ++e) t += wr[e] * b2[e];
        g_b2i[s] = binv[s] + t;
    }
}

__global__ void prep_w2p() {
    int id   = blockIdx.x * 256 + threadIdx.x;   // 16384
    int comp = id & 7;
    int l    = (id >> 3) & 31;
    int sh   = (id >> 8) & 1;
    int ksl  = (id >> 9) & 7;
    int kq   = (id >> 12) & 3;
    int g = l >> 2, tg = l & 3;
    int nt2 = comp >> 1, hh = comp & 1;
    int h = 8 * (kq * 8 + ksl) + tg + 4 * hh;
    int s = 32 * sh + 8 * nt2 + g;
    ((uint32_t*)g_W2p)[id] = f2tf32(g_W2T[h * SEG + s]);
}

// ---------------- main kernel: 1 elem/CTA, producer/consumer warp groups ----
// smem float offsets (~173.5 KB -> 1 CTA/SM)
#define OFF_ENC  0        // 16896  2 pair-buffers x 2ch x [32][132] raw fp32
#define OFF_HA   16896    // 16384  2 x hA[2048 uint4-rows] (tf32, swizzled)
#define OFF_SEG  33280    // 8704   4 partial seg [32][68]
#define OFF_SIG  41984    // 1058
#define OFF_B1   43042    // 256
#define OFF_B2   43298    // 64
#define OFF_WCV  43362    // 24
#define SMEM_FLOATS 43392
#define SMEM_BYTES  (SMEM_FLOATS * 4)

// barrier ids: 1,2 = full(buf0,buf1); 3,4 = empty(buf0,buf1); 5 = producers; 6 = consumers
__device__ __forceinline__ float cinvf(int p) {
    return (p < 32 || p >= 1024) ? 1.0f : 0.5f;
}

__global__ __launch_bounds__(THREADS, 1)
void decoder_main(const float* __restrict__ enc, const float* __restrict__ b1,
                  const float* __restrict__ Wconv, const float* __restrict__ bconv,
                  float* __restrict__ out) {
    extern __shared__ float sm[];
    uint32_t* hAU  = (uint32_t*)(sm + OFF_HA);
    float*    segB = sm + OFF_SEG;
    float*    sig  = sm + OFF_SIG;
    float*    b1s  = sm + OFF_B1;
    float*    b2s  = sm + OFF_B2;
    float*    wcv  = sm + OFF_WCV;
    const uint32_t smemBase = (uint32_t)__cvta_generic_to_shared(sm);

    const int tid = threadIdx.x;
    const int l   = tid & 31;
    const int w   = tid >> 5;       // 0..15
    const int g   = l >> 2;
    const int tg  = l & 3;
    const int b   = blockIdx.x;     // batch element

    if (tid < NH)  b1s[tid] = b1[tid];
    if (tid < SEG) b2s[tid] = g_b2i[tid];
    if (tid < 24)  wcv[tid] = Wconv[tid];
    if (tid == 0) { sig[0] = 0.f; sig[1057] = 0.f; }
    __syncthreads();

    if (w < 8) {
        // ================= PRODUCER: cp.async + GEMM1 + epilogue =================
        // stage enc pair 0 into buffer 0
        {
            #pragma unroll
            for (int ch = 0; ch < 2; ++ch) {
                const float* src = enc + (size_t)(b * NC + ch) * (NT * NE);
                #pragma unroll
                for (int r = 0; r < 4; ++r) {
                    int fi = tid + 256 * r;
                    int m = fi >> 5, kk = fi & 31;
                    cpasync16(smemBase +
                              (uint32_t)(OFF_ENC + ch * 4224 + m * 132 + kk * 4) * 4,
                              src + fi * 4);
                }
            }
            CPASYNC_COMMIT();
        }

        for (int cp = 0; cp < 4; ++cp) {
            const int pb = cp & 1;
            const uint32_t* encU = (const uint32_t*)(sm + OFF_ENC + pb * 8448);
            CPASYNC_WAIT0();
            BARS(5, 256);   // producers see staged enc

            // ---- GEMM1 both channels, B loaded once per pair ----
            float c1[2][2][4][4];
            #pragma unroll
            for (int nt = 0; nt < 4; ++nt) {
                float bb0 = b1s[32 * w + 8 * nt + 2 * tg];
                float bb1 = b1s[32 * w + 8 * nt + 2 * tg + 1];
                #pragma unroll
                for (int ch = 0; ch < 2; ++ch)
                    #pragma unroll
                    for (int mt = 0; mt < 2; ++mt) {
                        c1[ch][mt][nt][0] = bb0; c1[ch][mt][nt][1] = bb1;
                        c1[ch][mt][nt][2] = bb0; c1[ch][mt][nt][3] = bb1;
                    }
            }
            {
                const uint4* W1g = (const uint4*)g_W1p;
                int bidx = w * 1024 + l * 2;
                uint4 B0 = __ldg(&W1g[bidx]);
                uint4 B1 = __ldg(&W1g[bidx + 1]);
                #pragma unroll
                for (int ks = 0; ks < 16; ++ks) {
                    uint4 nB0, nB1;
                    if (ks < 15) {
                        nB0 = __ldg(&W1g[bidx + 64 * (ks + 1)]);
                        nB1 = __ldg(&W1g[bidx + 64 * (ks + 1) + 1]);
                    }
                    #pragma unroll
                    for (int ch = 0; ch < 2; ++ch) {
                        const uint32_t* eU = encU + ch * 4224;
                        #pragma unroll
                        for (int mt = 0; mt < 2; ++mt) {
                            uint32_t a[4];
                            int r0 = (mt * 16 + g) * 132;
                            int k0 = 8 * ks + tg;
                            a[0] = eU[r0 + k0];
                            a[1] = eU[r0 + 8 * 132 + k0];
                            a[2] = eU[r0 + k0 + 4];
                            a[3] = eU[r0 + 8 * 132 + k0 + 4];
                            MMA_TF32(c1[ch][mt][0], a, B0.x, B0.y);
                            MMA_TF32(c1[ch][mt][1], a, B0.z, B0.w);
                            MMA_TF32(c1[ch][mt][2], a, B1.x, B1.y);
                            MMA_TF32(c1[ch][mt][3], a, B1.z, B1.w);
                        }
                    }
                    B0 = nB0; B1 = nB1;
                }
            }

            // ---- prefetch next pair into the other enc buffer ----
            if (cp < 3) {
                #pragma unroll
                for (int ch = 0; ch < 2; ++ch) {
                    const float* src =
                        enc + (size_t)(b * NC + 2 * (cp + 1) + ch) * (NT * NE);
                    #pragma unroll
                    for (int r = 0; r < 4; ++r) {
                        int fi = tid + 256 * r;
                        int m = fi >> 5, kk = fi & 31;
                        cpasync16(smemBase +
                            (uint32_t)(OFF_ENC + (pb ^ 1) * 8448 + ch * 4224 +
                                       m * 132 + kk * 4) * 4,
                            src + fi * 4);
                    }
                }
                CPASYNC_COMMIT();
            }

            // ---- epilogue per channel into hA[sub] (swizzled) ----
            {
                int col0 = 2 * tg, col1 = 2 * tg + 1;
                int i00 = (4 * g + (col0 & 3)) * 4 + 2 * (col0 >= 4);
                int i01 = (4 * g + (col1 & 3)) * 4 + 2 * (col1 >= 4);
                int c00 = i00 >> 2, c01 = i01 >> 2;
                int j00 = ((c00 ^ ((c00 >> 3) & 7)) << 2) + (i00 & 3);
                int j01 = ((c01 ^ ((c01 >> 3) & 7)) << 2) + (i01 & 3);
                #pragma unroll
                for (int sub = 0; sub < 2; ++sub) {
                    if (cp > 0) BARS(3 + sub, 512);   // wait buffer empty
                    #pragma unroll
                    for (int mt = 0; mt < 2; ++mt)
                        #pragma unroll
                        for (int nt = 0; nt < 4; ++nt) {
                            uint32_t* bp =
                                hAU + sub * 8192 + (mt * 32 + (4 * w + nt)) * 128;
                            uint2 u0, u1;
                            u0.x = f2tf32(fmaxf(c1[sub][mt][nt][0], 0.f));
                            u0.y = f2tf32(fmaxf(c1[sub][mt][nt][2], 0.f));
                            u1.x = f2tf32(fmaxf(c1[sub][mt][nt][1], 0.f));
                            u1.y = f2tf32(fmaxf(c1[sub][mt][nt][3], 0.f));
                            *(uint2*)(bp + j00) = u0;
                            *(uint2*)(bp + j01) = u1;
                        }
                    MEMBAR_CTA();
                    BARA(1 + sub, 512);               // signal buffer full
                }
            }
        }
    } else {
        // ================= CONSUMER: GEMM2 + overlap-add + conv =================
        const int wc  = w - 8;          // 0..7
        const int kq  = wc >> 1;        // GEMM2 K-quarter
        const int sh  = wc & 1;         // GEMM2 s-half
        const int lsw = l ^ ((l >> 3) & 7);
        const int ctid = tid - 256;     // 0..255

        float oa[5];
        #pragma unroll
        for (int i = 0; i < 5; ++i) oa[i] = 0.f;

        for (int c = 0; c < NC; ++c) {
            const int buf = c & 1;
            BARS(1 + buf, 512);          // wait hA full

            // ---- GEMM2: K-split 4, s-split 2, n32 per warp ----
            float c2[2][4][4];
            {
                const uint4* hU4 = (const uint4*)(hAU + buf * 8192);
                const uint4* W2g = (const uint4*)g_W2p;
                #pragma unroll
                for (int nt2 = 0; nt2 < 4; ++nt2) {
                    float bb0 = (kq == 0) ? b2s[32 * sh + 8 * nt2 + 2 * tg] : 0.f;
                    float bb1 = (kq == 0) ? b2s[32 * sh + 8 * nt2 + 2 * tg + 1] : 0.f;
                    #pragma unroll
                    for (int mt = 0; mt < 2; ++mt) {
                        c2[mt][nt2][0] = bb0; c2[mt][nt2][1] = bb1;
                        c2[mt][nt2][2] = bb0; c2[mt][nt2][3] = bb1;
                    }
                }
                int b2idx = (((kq * 8) * 2 + sh) * 32 + l) * 2;
                uint4 Bv0 = __ldg(&W2g[b2idx]);
                uint4 Bv1 = __ldg(&W2g[b2idx + 1]);
                #pragma unroll
                for (int ksl = 0; ksl < 8; ++ksl) {
                    uint4 nBv0, nBv1;
                    if (ksl < 7) {
                        nBv0 = __ldg(&W2g[b2idx + 128 * (ksl + 1)]);
                        nBv1 = __ldg(&W2g[b2idx + 128 * (ksl + 1) + 1]);
                    }
                    int ks2 = kq * 8 + ksl;
                    uint4 A0 = hU4[(0 * 32 + ks2) * 32 + lsw];
                    uint4 A1 = hU4[(1 * 32 + ks2) * 32 + lsw];
                    MMA_TF32(c2[0][0], (&A0.x), Bv0.x, Bv0.y);
                    MMA_TF32(c2[0][1], (&A0.x), Bv0.z, Bv0.w);
                    MMA_TF32(c2[0][2], (&A0.x), Bv1.x, Bv1.y);
                    MMA_TF32(c2[0][3], (&A0.x), Bv1.z, Bv1.w);
                    MMA_TF32(c2[1][0], (&A1.x), Bv0.x, Bv0.y);
                    MMA_TF32(c2[1][1], (&A1.x), Bv0.z, Bv0.w);
                    MMA_TF32(c2[1][2], (&A1.x), Bv1.x, Bv1.y);
                    MMA_TF32(c2[1][3], (&A1.x), Bv1.z, Bv1.w);
                    Bv0 = nBv0; Bv1 = nBv1;
                }
            }
            BARA(3 + buf, 512);          // hA consumed -> producer may refill

            // ---- store partial seg (kq buffer, no RMW) ----
            {
                float* sp = segB + kq * 2176;
                #pragma unroll
                for (int mt = 0; mt < 2; ++mt)
                    #pragma unroll
                    for (int nt2 = 0; nt2 < 4; ++nt2) {
                        int s0 = 32 * sh + 8 * nt2 + 2 * tg;
                        float2 v0 = make_float2(c2[mt][nt2][0], c2[mt][nt2][1]);
                        float2 v1 = make_float2(c2[mt][nt2][2], c2[mt][nt2][3]);
                        *(float2*)&sp[(mt * 16 + g) * 68 + s0]     = v0;
                        *(float2*)&sp[(mt * 16 + g + 8) * 68 + s0] = v1;
                    }
            }
            BARS(6, 256);

            // ---- overlap-add + normalize -> sig ----
            #pragma unroll
            for (int i = 0; i < 5; ++i) {
                int p = ctid + 256 * i;
                if (p < SIG) {
                    int t = p >> 5, s = p & 31;
                    float v = 0.f;
                    #pragma unroll
                    for (int q = 0; q < 4; ++q) {
                        const float* sp = segB + q * 2176;
                        if (t < 32) v += sp[t * 68 + s];
                        if (t > 0)  v += sp[(t - 1) * 68 + s + 32];
                    }
                    sig[1 + p] = v * cinvf(p);
                }
            }
            BARS(6, 256);

            // ---- conv tap -> oa ----
            {
                float w0c = wcv[c * 3 + 0];
                float w1c = wcv[c * 3 + 1];
                float w2c = wcv[c * 3 + 2];
                #pragma unroll
                for (int i = 0; i < 5; ++i) {
                    int p = ctid + 256 * i;
                    if (p < SIG)
                        oa[i] += w0c * sig[p] + w1c * sig[p + 1] + w2c * sig[p + 2];
                }
            }
        }

        float bc = bconv[0];
        #pragma unroll
        for (int i = 0; i < 5; ++i) {
            int p = ctid + 256 * i;
            if (p < SIG) out[(size_t)b * SIG + p] = oa[i] + bc;
        }
    }
}

// ---------------- launch ----------------
extern "C" void kernel_launch(void* const* d_in, const int* in_sizes, int n_in,
                              void* d_out, int out_size) {
    (void)in_sizes; (void)n_in; (void)out_size;
    const float* enc   = (const float*)d_in[0];
    const float* W1    = (const float*)d_in[1];
    const float* b1    = (const float*)d_in[2];
    const float* W2    = (const float*)d_in[3];
    const float* b2    = (const float*)d_in[4];
    const float* Winv  = (const float*)d_in[5];
    const float* binv  = (const float*)d_in[6];
    const float* Wconv = (const float*)d_in[7];
    const float* bconv = (const float*)d_in[8];
    float* out = (float*)d_out;

    cudaFuncSetAttribute(decoder_main, cudaFuncAttributeMaxDynamicSharedMemorySize,
                         SMEM_BYTES);

    prep_w1p<<<128, 256>>>(W1);
    prep_w2<<<64, 256>>>(W2, Winv, b2, binv);
    prep_w2p<<<64, 256>>>();
    decoder_main<<<NB, THREADS, SMEM_BYTES>>>(enc, b1, Wconv, bconv, out);
}

// round 13
// speedup vs baseline: 1.6236x; 1.6236x over previous
#include <cuda_runtime.h>
#include <cstdint>
#include <cstddef>

#define NB   1024
#define NC   8
#define NT   32
#define NE   128
#define NH   256
#define SEG  64
#define SIG  1056

// ---------------- device scratch (static; no allocations) ----------------
__device__ __align__(16) uint32_t g_W1h[8 * 8 * 32 * 8];   // 16384 f16x2 words, GEMM1-B pack
__device__ __align__(16) float    g_W2T[NH * SEG];         // [h][s] = (Winv@W2)^T
__device__ __align__(16) uint32_t g_W2h[4 * 4 * 2 * 32 * 8]; // 8192 f16x2 words, GEMM2-B pack
__device__ __align__(16) float    g_b2i[SEG];              // binv + Winv@b2

// ---------------- helpers ----------------
__device__ __forceinline__ uint32_t f2h2(float lo, float hi) {
    uint32_t u;
    asm("cvt.rn.f16x2.f32 %0, %1, %2;" : "=r"(u) : "f"(hi), "f"(lo));
    return u;
}
__device__ __forceinline__ void cpasync16(uint32_t saddr, const void* gaddr) {
    asm volatile("cp.async.cg.shared.global [%0], [%1], 16;" :: "r"(saddr), "l"(gaddr));
}
#define CPASYNC_COMMIT() asm volatile("cp.async.commit_group;")
#define CPASYNC_WAIT0()  asm volatile("cp.async.wait_group 0;")

#define MMA_F16(C, A, b0v, b1v)                                                \
    asm volatile(                                                              \
        "mma.sync.aligned.m16n8k16.row.col.f32.f16.f16.f32 "                   \
        "{%0,%1,%2,%3},{%4,%5,%6,%7},{%8,%9},{%0,%1,%2,%3};"                   \
        : "+f"((C)[0]), "+f"((C)[1]), "+f"((C)[2]), "+f"((C)[3])               \
        : "r"((A)[0]), "r"((A)[1]), "r"((A)[2]), "r"((A)[3]),                  \
          "r"(b0v), "r"(b1v))

// ---------------- prep kernels ----------------
// GEMM1-B pack: g_W1h[((w*8+ks)*32+l)*8 + nt*2+r] =
//   f16x2{ W1[j][k0], W1[j][k0+1] }, j = 32w+8nt+g, k0 = 16ks+2tg+8r
__global__ void prep_w1h(const float* __restrict__ W1) {
    int id = blockIdx.x * 256 + threadIdx.x;     // 16384
    int v  = id & 7;
    int l  = (id >> 3) & 31;
    int ks = (id >> 8) & 7;
    int w  = (id >> 11) & 7;
    int g = l >> 2, tg = l & 3, nt = v >> 1, r = v & 1;
    int j  = 32 * w + 8 * nt + g;
    int k0 = 16 * ks + 2 * tg + 8 * r;
    g_W1h[id] = f2h2(W1[j * NE + k0], W1[j * NE + k0 + 1]);
}

// W2T[h][s] = sum_e Winv[s][e]*W2[e][h];  b2i[s] = binv[s] + Winv[s]·b2
__global__ void prep_w2(const float* __restrict__ W2, const float* __restrict__ Winv,
                        const float* __restrict__ b2, const float* __restrict__ binv) {
    int s = blockIdx.x;        // 64
    int h = threadIdx.x;       // 256
    const float* wr = Winv + s * NE;
    float acc = 0.f;
    #pragma unroll 4
    for (int e = 0; e < NE; ++e) acc += wr[e] * W2[e * NH + h];
    g_W2T[h * SEG + s] = acc;
    if (h == 0) {
        float t = 0.f;
        for (int e = 0; e < NE; ++e) t += wr[e] * b2[e];
        g_b2i[s] = binv[s] + t;
    }
}

// GEMM2-B pack: g_W2h[(((kq*4+ksl)*2+sh)*32+l)*8 + nt2*2+r] =
//   f16x2{ W2T[k0][s], W2T[k0+1][s] }, k0 = 16*(4kq+ksl)+2tg+8r, s = 32sh+8nt2+g
__global__ void prep_w2h() {
    int id  = blockIdx.x * 256 + threadIdx.x;    // 8192
    int v   = id & 7;
    int l   = (id >> 3) & 31;
    int sh  = (id >> 8) & 1;
    int ksl = (id >> 9) & 3;
    int kq  = (id >> 11) & 3;
    int g = l >> 2, tg = l & 3, nt2 = v >> 1, r = v & 1;
    int k0 = 16 * (4 * kq + ksl) + 2 * tg + 8 * r;
    int s  = 32 * sh + 8 * nt2 + g;
    g_W2h[id] = f2h2(g_W2T[k0 * SEG + s], g_W2T[(k0 + 1) * SEG + s]);
}

// ---------------- main kernel ----------------
// smem float offsets (~107.5 KB -> 2 CTAs/SM)
#define OFF_E32  0        // 8192   pair fp32 enc (cp.async target, linear)
#define OFF_EH   8192     // 4352   2ch fp16 enc tiles [32 rows][68 words]
#define OFF_HA   12544    // 4224   hA fp16 [32 rows][132 words]
#define OFF_SEG  16768    // 8704   4 partial seg [32][68] fp32
#define OFF_SIG  25472    // 1058
#define OFF_B1   26530    // 256
#define OFF_B2   26786    // 64
#define OFF_WCV  26850    // 24
#define SMEM_FLOATS 26880
#define SMEM_BYTES  (SMEM_FLOATS * 4)

__device__ __forceinline__ float cinvf(int p) {
    return (p < 32 || p >= 1024) ? 1.0f : 0.5f;   // 1/overlap-count
}

__global__ __launch_bounds__(256, 2)
void decoder_main(const float* __restrict__ enc, const float* __restrict__ b1,
                  const float* __restrict__ Wconv, const float* __restrict__ bconv,
                  float* __restrict__ out) {
    extern __shared__ float sm[];
    const float4* e32f4 = (const float4*)(sm + OFF_E32);
    uint32_t*     ehW   = (uint32_t*)(sm + OFF_EH);
    uint32_t*     hAW   = (uint32_t*)(sm + OFF_HA);
    float*        segB  = sm + OFF_SEG;
    float*        sig   = sm + OFF_SIG;
    float*        b1s   = sm + OFF_B1;
    float*        b2s   = sm + OFF_B2;
    float*        wcv   = sm + OFF_WCV;
    const uint32_t smemBase = (uint32_t)__cvta_generic_to_shared(sm);

    const int tid = threadIdx.x;
    const int l   = tid & 31;
    const int w   = tid >> 5;       // warp 0..7
    const int g   = l >> 2;
    const int tg  = l & 3;
    const int b   = blockIdx.x;
    const int kq  = w >> 1;         // GEMM2 K-quarter
    const int sh  = w & 1;          // GEMM2 s-half

    b1s[tid] = b1[tid];
    if (tid < SEG) b2s[tid] = g_b2i[tid];
    if (tid < 24)  wcv[tid] = Wconv[tid];
    if (tid == 0) { sig[0] = 0.f; sig[1057] = 0.f; }

    float oa[5];
    #pragma unroll
    for (int i = 0; i < 5; ++i) oa[i] = 0.f;

    // ---- prologue: cp.async pair 0 (fp32, linear) ----
    {
        const float* src = enc + (size_t)b * NC * (NT * NE);
        #pragma unroll
        for (int i = 0; i < 8; ++i) {
            int fi = tid + 256 * i;
            cpasync16(smemBase + (uint32_t)(OFF_E32 * 4 + fi * 16), src + fi * 4);
        }
        CPASYNC_COMMIT();
    }

    for (int cp = 0; cp < 4; ++cp) {
        CPASYNC_WAIT0();
        __syncthreads();

        // ---- convert fp32 -> fp16 tiles [ch][row*68 + word] ----
        #pragma unroll
        for (int i = 0; i < 8; ++i) {
            int fi = tid + 256 * i;
            int ch = fi >> 10, rem = fi & 1023;
            int row = rem >> 5, kk = rem & 31;
            float4 v = e32f4[fi];
            uint2 u;
            u.x = f2h2(v.x, v.y);
            u.y = f2h2(v.z, v.w);
            *(uint2*)(ehW + ch * 2176 + row * 68 + 2 * kk) = u;
        }
        __syncthreads();

        // ---- prefetch next pair into freed fp32 buffer ----
        if (cp < 3) {
            const float* src = enc + ((size_t)b * NC + 2 * (cp + 1)) * (NT * NE);
            #pragma unroll
            for (int i = 0; i < 8; ++i) {
                int fi = tid + 256 * i;
                cpasync16(smemBase + (uint32_t)(OFF_E32 * 4 + fi * 16), src + fi * 4);
            }
            CPASYNC_COMMIT();
        }

        // ---- GEMM1 (fp16): both channels, B loaded once per pair ----
        float c1[2][2][4][4];                       // [ch][mt][nt][4]
        #pragma unroll
        for (int nt = 0; nt < 4; ++nt) {
            float bb0 = b1s[32 * w + 8 * nt + 2 * tg];
            float bb1 = b1s[32 * w + 8 * nt + 2 * tg + 1];
            #pragma unroll
            for (int ch = 0; ch < 2; ++ch)
                #pragma unroll
                for (int mt = 0; mt < 2; ++mt) {
                    c1[ch][mt][nt][0] = bb0; c1[ch][mt][nt][1] = bb1;
                    c1[ch][mt][nt][2] = bb0; c1[ch][mt][nt][3] = bb1;
                }
        }
        {
            const uint4* W1g = (const uint4*)g_W1h;
            int bidx = w * 512 + l * 2;             // ((w*8+ks)*32+l)*2, ks=0
            uint4 B0 = __ldg(&W1g[bidx]);
            uint4 B1 = __ldg(&W1g[bidx + 1]);
            #pragma unroll
            for (int ks = 0; ks < 8; ++ks) {
                uint4 nB0, nB1;
                if (ks < 7) {
                    nB0 = __ldg(&W1g[bidx + 64 * (ks + 1)]);
                    nB1 = __ldg(&W1g[bidx + 64 * (ks + 1) + 1]);
                }
                #pragma unroll
                for (int ch = 0; ch < 2; ++ch) {
                    const uint32_t* eW = ehW + ch * 2176;
                    #pragma unroll
                    for (int mt = 0; mt < 2; ++mt) {
                        uint32_t a[4];
                        int r0 = (16 * mt + g) * 68;
                        int k0 = 8 * ks + tg;
                        a[0] = eW[r0 + k0];
                        a[1] = eW[r0 + 8 * 68 + k0];
                        a[2] = eW[r0 + k0 + 4];
                        a[3] = eW[r0 + 8 * 68 + k0 + 4];
                        MMA_F16(c1[ch][mt][0], a, B0.x, B0.y);
                        MMA_F16(c1[ch][mt][1], a, B0.z, B0.w);
                        MMA_F16(c1[ch][mt][2], a, B1.x, B1.y);
                        MMA_F16(c1[ch][mt][3], a, B1.z, B1.w);
                    }
                }
                B0 = nB0; B1 = nB1;
            }
        }

        for (int sub = 0; sub < 2; ++sub) {
            // ---- epilogue: ReLU, pack f16x2 -> hA[row][132] ----
            {
                int jp = 16 * w + tg;               // + 4*nt below
                #pragma unroll
                for (int mt = 0; mt < 2; ++mt)
                    #pragma unroll
                    for (int nt = 0; nt < 4; ++nt) {
                        float r0a = fmaxf(c1[sub][mt][nt][0], 0.f);
                        float r0b = fmaxf(c1[sub][mt][nt][1], 0.f);
                        float r1a = fmaxf(c1[sub][mt][nt][2], 0.f);
                        float r1b = fmaxf(c1[sub][mt][nt][3], 0.f);
                        hAW[(16 * mt + g) * 132 + jp + 4 * nt]     = f2h2(r0a, r0b);
                        hAW[(16 * mt + g + 8) * 132 + jp + 4 * nt] = f2h2(r1a, r1b);
                    }
            }
            __syncthreads();

            // ---- GEMM2 (fp16): K-split 4, s-split 2, n32 per warp ----
            float c2[2][4][4];                      // [mt][nt2][4]
            {
                #pragma unroll
                for (int nt2 = 0; nt2 < 4; ++nt2) {
                    float bb0 = (kq == 0) ? b2s[32 * sh + 8 * nt2 + 2 * tg] : 0.f;
                    float bb1 = (kq == 0) ? b2s[32 * sh + 8 * nt2 + 2 * tg + 1] : 0.f;
                    #pragma unroll
                    for (int mt = 0; mt < 2; ++mt) {
                        c2[mt][nt2][0] = bb0; c2[mt][nt2][1] = bb1;
                        c2[mt][nt2][2] = bb0; c2[mt][nt2][3] = bb1;
                    }
                }
                const uint4* W2g = (const uint4*)g_W2h;
                int b2idx = (((kq * 4) * 2 + sh) * 32 + l) * 2;
                uint4 Bv0 = __ldg(&W2g[b2idx]);
                uint4 Bv1 = __ldg(&W2g[b2idx + 1]);
                #pragma unroll
                for (int ksl = 0; ksl < 4; ++ksl) {
                    uint4 nBv0, nBv1;
                    if (ksl < 3) {
                        nBv0 = __ldg(&W2g[b2idx + 128 * (ksl + 1)]);
                        nBv1 = __ldg(&W2g[b2idx + 128 * (ksl + 1) + 1]);
                    }
                    int k0 = 8 * (4 * kq + ksl) + tg;
                    #pragma unroll
                    for (int mt = 0; mt < 2; ++mt) {
                        uint32_t a[4];
                        int r0 = (16 * mt + g) * 132;
                        a[0] = hAW[r0 + k0];
                        a[1] = hAW[r0 + 8 * 132 + k0];
                        a[2] = hAW[r0 + k0 + 4];
                        a[3] = hAW[r0 + 8 * 132 + k0 + 4];
                        MMA_F16(c2[mt][0], a, Bv0.x, Bv0.y);
                        MMA_F16(c2[mt][1], a, Bv0.z, Bv0.w);
                        MMA_F16(c2[mt][2], a, Bv1.x, Bv1.y);
                        MMA_F16(c2[mt][3], a, Bv1.z, Bv1.w);
                    }
                    Bv0 = nBv0; Bv1 = nBv1;
                }
            }

            // ---- store partial seg (kq buffer, no RMW) ----
            {
                float* sp = segB + kq * 2176;
                #pragma unroll
                for (int mt = 0; mt < 2; ++mt)
                    #pragma unroll
                    for (int nt2 = 0; nt2 < 4; ++nt2) {
                        int s0 = 32 * sh + 8 * nt2 + 2 * tg;
                        float2 v0 = make_float2(c2[mt][nt2][0], c2[mt][nt2][1]);
                        float2 v1 = make_float2(c2[mt][nt2][2], c2[mt][nt2][3]);
                        *(float2*)&sp[(16 * mt + g) * 68 + s0]     = v0;
                        *(float2*)&sp[(16 * mt + g + 8) * 68 + s0] = v1;
                    }
            }
            __syncthreads();

            // ---- overlap-add + normalize -> sig ----
            for (int p = tid; p < SIG; p += 256) {
                int t = p >> 5, s = p & 31;
                float v = 0.f;
                #pragma unroll
                for (int q = 0; q < 4; ++q) {
                    const float* sp = segB + q * 2176;
                    if (t < 32) v += sp[t * 68 + s];
                    if (t > 0)  v += sp[(t - 1) * 68 + s + 32];
                }
                sig[1 + p] = v * cinvf(p);
            }
            __syncthreads();

            // ---- conv tap -> oa ----
            {
                int c = 2 * cp + sub;
                float w0c = wcv[c * 3 + 0];
                float w1c = wcv[c * 3 + 1];
                float w2c = wcv[c * 3 + 2];
                #pragma unroll
                for (int i = 0; i < 5; ++i) {
                    int p = tid + 256 * i;
                    if (p < SIG)
                        oa[i] += w0c * sig[p] + w1c * sig[p + 1] + w2c * sig[p + 2];
                }
            }
            __syncthreads();
        }
    }

    float bc = bconv[0];
    #pragma unroll
    for (int i = 0; i < 5; ++i) {
        int p = tid + 256 * i;
        if (p < SIG) out[(size_t)b * SIG + p] = oa[i] + bc;
    }
}

// ---------------- launch ----------------
extern "C" void kernel_launch(void* const* d_in, const int* in_sizes, int n_in,
                              void* d_out, int out_size) {
    (void)in_sizes; (void)n_in; (void)out_size;
    const float* enc   = (const float*)d_in[0];
    const float* W1    = (const float*)d_in[1];
    const float* b1    = (const float*)d_in[2];
    const float* W2    = (const float*)d_in[3];
    const float* b2    = (const float*)d_in[4];
    const float* Winv  = (const float*)d_in[5];
    const float* binv  = (const float*)d_in[6];
    const float* Wconv = (const float*)d_in[7];
    const float* bconv = (const float*)d_in[8];
    float* out = (float*)d_out;

    cudaFuncSetAttribute(decoder_main, cudaFuncAttributeMaxDynamicSharedMemorySize,
                         SMEM_BYTES);

    prep_w1h<<<64, 256>>>(W1);
    prep_w2<<<64, 256>>>(W2, Winv, b2, binv);
    prep_w2h<<<32, 256>>>();
    decoder_main<<<NB, 256, SMEM_BYTES>>>(enc, b1, Wconv, bconv, out);
}

// round 14
// speedup vs baseline: 1.6280x; 1.0027x over previous
#include <cuda_runtime.h>
#include <cstdint>
#include <cstddef>

#define NB   1024
#define NC   8
#define NT   32
#define NE   128
#define NH   256
#define SEG  64
#define SIG  1056

// ---------------- device scratch (static; no allocations) ----------------
__device__ __align__(16) uint32_t g_W1h[8 * 8 * 32 * 8];   // 16384 f16x2 words, GEMM1-B pack
__device__ __align__(16) float    g_W2T[NH * SEG];         // [h][s] = (Winv@W2)^T
__device__ __align__(16) uint32_t g_W2h[4 * 4 * 2 * 32 * 8]; // 8192 f16x2 words, GEMM2-B pack
__device__ __align__(16) float    g_b2i[SEG];              // binv + Winv@b2

// ---------------- helpers ----------------
__device__ __forceinline__ uint32_t f2h2(float lo, float hi) {
    uint32_t u;
    asm("cvt.rn.f16x2.f32 %0, %1, %2;" : "=r"(u) : "f"(hi), "f"(lo));
    return u;
}
__device__ __forceinline__ void cpasync16(uint32_t saddr, const void* gaddr) {
    asm volatile("cp.async.cg.shared.global [%0], [%1], 16;" :: "r"(saddr), "l"(gaddr));
}
#define CPASYNC_COMMIT() asm volatile("cp.async.commit_group;")
#define CPASYNC_WAIT0()  asm volatile("cp.async.wait_group 0;")

#define MMA_F16(C, A, b0v, b1v)                                                \
    asm volatile(                                                              \
        "mma.sync.aligned.m16n8k16.row.col.f32.f16.f16.f32 "                   \
        "{%0,%1,%2,%3},{%4,%5,%6,%7},{%8,%9},{%0,%1,%2,%3};"                   \
        : "+f"((C)[0]), "+f"((C)[1]), "+f"((C)[2]), "+f"((C)[3])               \
        : "r"((A)[0]), "r"((A)[1]), "r"((A)[2]), "r"((A)[3]),                  \
          "r"(b0v), "r"(b1v))

// ---------------- prep kernels ----------------
// GEMM1-B pack: g_W1h[((w*8+ks)*32+l)*8 + nt*2+r] =
//   f16x2{ W1[j][k0], W1[j][k0+1] }, j = 32w+8nt+g, k0 = 16ks+2tg+8r
__global__ void prep_w1h(const float* __restrict__ W1) {
    int id = blockIdx.x * 256 + threadIdx.x;     // 16384
    int v  = id & 7;
    int l  = (id >> 3) & 31;
    int ks = (id >> 8) & 7;
    int w  = (id >> 11) & 7;
    int g = l >> 2, tg = l & 3, nt = v >> 1, r = v & 1;
    int j  = 32 * w + 8 * nt + g;
    int k0 = 16 * ks + 2 * tg + 8 * r;
    g_W1h[id] = f2h2(W1[j * NE + k0], W1[j * NE + k0 + 1]);
}

// W2T[h][s] = sum_e Winv[s][e]*W2[e][h];  b2i[s] = binv[s] + Winv[s]·b2
__global__ void prep_w2(const float* __restrict__ W2, const float* __restrict__ Winv,
                        const float* __restrict__ b2, const float* __restrict__ binv) {
    int s = blockIdx.x;        // 64
    int h = threadIdx.x;       // 256
    const float* wr = Winv + s * NE;
    float acc = 0.f;
    #pragma unroll 4
    for (int e = 0; e < NE; ++e) acc += wr[e] * W2[e * NH + h];
    g_W2T[h * SEG + s] = acc;
    if (h == 0) {
        float t = 0.f;
        for (int e = 0; e < NE; ++e) t += wr[e] * b2[e];
        g_b2i[s] = binv[s] + t;
    }
}

// GEMM2-B pack: g_W2h[(((kq*4+ksl)*2+sh)*32+l)*8 + nt2*2+r] =
//   f16x2{ W2T[k0][s], W2T[k0+1][s] }, k0 = 16*(4kq+ksl)+2tg+8r, s = 32sh+8nt2+g
__global__ void prep_w2h() {
    int id  = blockIdx.x * 256 + threadIdx.x;    // 8192
    int v   = id & 7;
    int l   = (id >> 3) & 31;
    int sh  = (id >> 8) & 1;
    int ksl = (id >> 9) & 3;
    int kq  = (id >> 11) & 3;
    int g = l >> 2, tg = l & 3, nt2 = v >> 1, r = v & 1;
    int k0 = 16 * (4 * kq + ksl) + 2 * tg + 8 * r;
    int s  = 32 * sh + 8 * nt2 + g;
    g_W2h[id] = f2h2(g_W2T[k0 * SEG + s], g_W2T[(k0 + 1) * SEG + s]);
}

// ---------------- main kernel ----------------
// smem float offsets (~107.5 KB -> 2 CTAs/SM)
#define OFF_E32  0        // 8192   pair fp32 enc (cp.async target, linear)
#define OFF_EH   8192     // 4352   2ch fp16 enc tiles [32 rows][68 words]
#define OFF_HA   12544    // 4224   hA fp16 [32 rows][132 words]
#define OFF_SEG  16768    // 8704   4 partial seg [32][68] fp32
#define OFF_SIG  25472    // 1058
#define OFF_B1   26530    // 256
#define OFF_B2   26786    // 64
#define OFF_WCV  26850    // 24
#define SMEM_FLOATS 26880
#define SMEM_BYTES  (SMEM_FLOATS * 4)

__device__ __forceinline__ float cinvf(int p) {
    return (p < 32 || p >= 1024) ? 1.0f : 0.5f;   // 1/overlap-count
}

__global__ __launch_bounds__(256, 2)
void decoder_main(const float* __restrict__ enc, const float* __restrict__ b1,
                  const float* __restrict__ Wconv, const float* __restrict__ bconv,
                  float* __restrict__ out) {
    extern __shared__ float sm[];
    const float4* e32f4 = (const float4*)(sm + OFF_E32);
    uint32_t*     ehW   = (uint32_t*)(sm + OFF_EH);
    uint32_t*     hAW   = (uint32_t*)(sm + OFF_HA);
    float*        segB  = sm + OFF_SEG;
    float*        sig   = sm + OFF_SIG;
    float*        b1s   = sm + OFF_B1;
    float*        b2s   = sm + OFF_B2;
    float*        wcv   = sm + OFF_WCV;
    const uint32_t smemBase = (uint32_t)__cvta_generic_to_shared(sm);

    const int tid = threadIdx.x;
    const int l   = tid & 31;
    const int w   = tid >> 5;       // warp 0..7
    const int g   = l >> 2;
    const int tg  = l & 3;
    const int b   = blockIdx.x;
    const int kq  = w >> 1;         // GEMM2 K-quarter
    const int sh  = w & 1;          // GEMM2 s-half

    b1s[tid] = b1[tid];
    if (tid < SEG) b2s[tid] = g_b2i[tid];
    if (tid < 24)  wcv[tid] = Wconv[tid];
    if (tid == 0) { sig[0] = 0.f; sig[1057] = 0.f; }

    float oa[5];
    #pragma unroll
    for (int i = 0; i < 5; ++i) oa[i] = 0.f;

    // conv tap accumulate for channel c (reads sig, writes oa regs only)
    auto conv_tap = [&](int c) {
        float w0c = wcv[c * 3 + 0];
        float w1c = wcv[c * 3 + 1];
        float w2c = wcv[c * 3 + 2];
        #pragma unroll
        for (int i = 0; i < 5; ++i) {
            int p = tid + 256 * i;
            if (p < SIG)
                oa[i] += w0c * sig[p] + w1c * sig[p + 1] + w2c * sig[p + 2];
        }
    };

    // ---- prologue: cp.async pair 0 (fp32, linear) ----
    {
        const float* src = enc + (size_t)b * NC * (NT * NE);
        #pragma unroll
        for (int i = 0; i < 8; ++i) {
            int fi = tid + 256 * i;
            cpasync16(smemBase + (uint32_t)(OFF_E32 * 4 + fi * 16), src + fi * 4);
        }
        CPASYNC_COMMIT();
    }

    for (int cp = 0; cp < 4; ++cp) {
        CPASYNC_WAIT0();
        __syncthreads();            // enc(pair cp) staged; sig(prev sub1) visible

        // ---- MERGED: convert fp32->fp16 tiles  +  deferred conv(ch 2cp-1) ----
        #pragma unroll
        for (int i = 0; i < 8; ++i) {
            int fi = tid + 256 * i;
            int ch = fi >> 10, rem = fi & 1023;
            int row = rem >> 5, kk = rem & 31;
            float4 v = e32f4[fi];
            uint2 u;
            u.x = f2h2(v.x, v.y);
            u.y = f2h2(v.z, v.w);
            *(uint2*)(ehW + ch * 2176 + row * 68 + 2 * kk) = u;
        }
        if (cp > 0) conv_tap(2 * cp - 1);
        __syncthreads();            // ehW ready; E32 consumed

        // ---- prefetch next pair into freed fp32 buffer ----
        if (cp < 3) {
            const float* src = enc + ((size_t)b * NC + 2 * (cp + 1)) * (NT * NE);
            #pragma unroll
            for (int i = 0; i < 8; ++i) {
                int fi = tid + 256 * i;
                cpasync16(smemBase + (uint32_t)(OFF_E32 * 4 + fi * 16), src + fi * 4);
            }
            CPASYNC_COMMIT();
        }

        // ---- GEMM1 (fp16): both channels, B loaded once per pair ----
        float c1[2][2][4][4];                       // [ch][mt][nt][4]
        #pragma unroll
        for (int nt = 0; nt < 4; ++nt) {
            float bb0 = b1s[32 * w + 8 * nt + 2 * tg];
            float bb1 = b1s[32 * w + 8 * nt + 2 * tg + 1];
            #pragma unroll
            for (int ch = 0; ch < 2; ++ch)
                #pragma unroll
                for (int mt = 0; mt < 2; ++mt) {
                    c1[ch][mt][nt][0] = bb0; c1[ch][mt][nt][1] = bb1;
                    c1[ch][mt][nt][2] = bb0; c1[ch][mt][nt][3] = bb1;
                }
        }
        {
            const uint4* W1g = (const uint4*)g_W1h;
            int bidx = w * 512 + l * 2;             // ((w*8+ks)*32+l)*2, ks=0
            uint4 B0 = __ldg(&W1g[bidx]);
            uint4 B1 = __ldg(&W1g[bidx + 1]);
            #pragma unroll
            for (int ks = 0; ks < 8; ++ks) {
                uint4 nB0, nB1;
                if (ks < 7) {
                    nB0 = __ldg(&W1g[bidx + 64 * (ks + 1)]);
                    nB1 = __ldg(&W1g[bidx + 64 * (ks + 1) + 1]);
                }
                #pragma unroll
                for (int ch = 0; ch < 2; ++ch) {
                    const uint32_t* eW = ehW + ch * 2176;
                    #pragma unroll
                    for (int mt = 0; mt < 2; ++mt) {
                        uint32_t a[4];
                        int r0 = (16 * mt + g) * 68;
                        int k0 = 8 * ks + tg;
                        a[0] = eW[r0 + k0];
                        a[1] = eW[r0 + 8 * 68 + k0];
                        a[2] = eW[r0 + k0 + 4];
                        a[3] = eW[r0 + 8 * 68 + k0 + 4];
                        MMA_F16(c1[ch][mt][0], a, B0.x, B0.y);
                        MMA_F16(c1[ch][mt][1], a, B0.z, B0.w);
                        MMA_F16(c1[ch][mt][2], a, B1.x, B1.y);
                        MMA_F16(c1[ch][mt][3], a, B1.z, B1.w);
                    }
                }
                B0 = nB0; B1 = nB1;
            }
        }

        #pragma unroll
        for (int sub = 0; sub < 2; ++sub) {
            // ---- MERGED: epilogue(sub)  +  conv(sub-1) for sub==1 ----
            {
                int jp = 16 * w + tg;               // + 4*nt below
                #pragma unroll
                for (int mt = 0; mt < 2; ++mt)
                    #pragma unroll
                    for (int nt = 0; nt < 4; ++nt) {
                        float r0a = fmaxf(c1[sub][mt][nt][0], 0.f);
                        float r0b = fmaxf(c1[sub][mt][nt][1], 0.f);
                        float r1a = fmaxf(c1[sub][mt][nt][2], 0.f);
                        float r1b = fmaxf(c1[sub][mt][nt][3], 0.f);
                        hAW[(16 * mt + g) * 132 + jp + 4 * nt]     = f2h2(r0a, r0b);
                        hAW[(16 * mt + g + 8) * 132 + jp + 4 * nt] = f2h2(r1a, r1b);
                    }
                if (sub == 1) conv_tap(2 * cp);     // sig(sub0) stable; disjoint smem
            }
            __syncthreads();

            // ---- GEMM2 (fp16): K-split 4, s-split 2, n32 per warp + seg store ----
            float c2[2][4][4];                      // [mt][nt2][4]
            {
                #pragma unroll
                for (int nt2 = 0; nt2 < 4; ++nt2) {
                    float bb0 = (kq == 0) ? b2s[32 * sh + 8 * nt2 + 2 * tg] : 0.f;
                    float bb1 = (kq == 0) ? b2s[32 * sh + 8 * nt2 + 2 * tg + 1] : 0.f;
                    #pragma unroll
                    for (int mt = 0; mt < 2; ++mt) {
                        c2[mt][nt2][0] = bb0; c2[mt][nt2][1] = bb1;
                        c2[mt][nt2][2] = bb0; c2[mt][nt2][3] = bb1;
                    }
                }
                const uint4* W2g = (const uint4*)g_W2h;
                int b2idx = (((kq * 4) * 2 + sh) * 32 + l) * 2;
                uint4 Bv0 = __ldg(&W2g[b2idx]);
                uint4 Bv1 = __ldg(&W2g[b2idx + 1]);
                #pragma unroll
                for (int ksl = 0; ksl < 4; ++ksl) {
                    uint4 nBv0, nBv1;
                    if (ksl < 3) {
                        nBv0 = __ldg(&W2g[b2idx + 128 * (ksl + 1)]);
                        nBv1 = __ldg(&W2g[b2idx + 128 * (ksl + 1) + 1]);
                    }
                    int k0 = 8 * (4 * kq + ksl) + tg;
                    #pragma unroll
                    for (int mt = 0; mt < 2; ++mt) {
                        uint32_t a[4];
                        int r0 = (16 * mt + g) * 132;
                        a[0] = hAW[r0 + k0];
                        a[1] = hAW[r0 + 8 * 132 + k0];
                        a[2] = hAW[r0 + k0 + 4];
                        a[3] = hAW[r0 + 8 * 132 + k0 + 4];
                        MMA_F16(c2[mt][0], a, Bv0.x, Bv0.y);
                        MMA_F16(c2[mt][1], a, Bv0.z, Bv0.w);
                        MMA_F16(c2[mt][2], a, Bv1.x, Bv1.y);
                        MMA_F16(c2[mt][3], a, Bv1.z, Bv1.w);
                    }
                    Bv0 = nBv0; Bv1 = nBv1;
                }
                float* sp = segB + kq * 2176;
                #pragma unroll
                for (int mt = 0; mt < 2; ++mt)
                    #pragma unroll
                    for (int nt2 = 0; nt2 < 4; ++nt2) {
                        int s0 = 32 * sh + 8 * nt2 + 2 * tg;
                        float2 v0 = make_float2(c2[mt][nt2][0], c2[mt][nt2][1]);
                        float2 v1 = make_float2(c2[mt][nt2][2], c2[mt][nt2][3]);
                        *(float2*)&sp[(16 * mt + g) * 68 + s0]     = v0;
                        *(float2*)&sp[(16 * mt + g + 8) * 68 + s0] = v1;
                    }
            }
            __syncthreads();

            // ---- overlap-add + normalize -> sig ----
            for (int p = tid; p < SIG; p += 256) {
                int t = p >> 5, s = p & 31;
                float v = 0.f;
                #pragma unroll
                for (int q = 0; q < 4; ++q) {
                    const float* sp = segB + q * 2176;
                    if (t < 32) v += sp[t * 68 + s];
                    if (t > 0)  v += sp[(t - 1) * 68 + s + 32];
                }
                sig[1 + p] = v * cinvf(p);
            }
            if (sub == 0) __syncthreads();  // sub1 uses loop-top / post-epilogue sync
        }
        __syncthreads();                    // sig(sub1) visible to next pair's conv
    }

    // ---- final deferred conv (channel 7) + output ----
    conv_tap(7);
    float bc = bconv[0];
    #pragma unroll
    for (int i = 0; i < 5; ++i) {
        int p = tid + 256 * i;
        if (p < SIG) out[(size_t)b * SIG + p] = oa[i] + bc;
    }
}

// ---------------- launch ----------------
extern "C" void kernel_launch(void* const* d_in, const int* in_sizes, int n_in,
                              void* d_out, int out_size) {
    (void)in_sizes; (void)n_in; (void)out_size;
    const float* enc   = (const float*)d_in[0];
    const float* W1    = (const float*)d_in[1];
    const float* b1    = (const float*)d_in[2];
    const float* W2    = (const float*)d_in[3];
    const float* b2    = (const float*)d_in[4];
    const float* Winv  = (const float*)d_in[5];
    const float* binv  = (const float*)d_in[6];
    const float* Wconv = (const float*)d_in[7];
    const float* bconv = (const float*)d_in[8];
    float* out = (float*)d_out;

    cudaFuncSetAttribute(decoder_main, cudaFuncAttributeMaxDynamicSharedMemorySize,
                         SMEM_BYTES);

    prep_w1h<<<64, 256>>>(W1);
    prep_w2<<<64, 256>>>(W2, Winv, b2, binv);
    prep_w2h<<<32, 256>>>();
    decoder_main<<<NB, 256, SMEM_BYTES>>>(enc, b1, Wconv, bconv, out);
}

// round 16
// speedup vs baseline: 1.6292x; 1.0008x over previous
#include <cuda_runtime.h>
#include <cstdint>
#include <cstddef>

#define NB   1024
#define NC   8
#define NT   32
#define NE   128
#define NH   256
#define SEG  64
#define SIG  1056

// ---------------- device scratch (static; no allocations) ----------------
__device__ __align__(16) uint32_t g_W1h[8 * 8 * 32 * 8];   // 16384 f16x2 words, GEMM1-B pack
__device__ __align__(16) float    g_W2T[NH * SEG];         // [h][s] = (Winv@W2)^T
__device__ __align__(16) uint32_t g_W2h[4 * 4 * 2 * 32 * 8]; // 8192 f16x2 words, GEMM2-B pack
__device__ __align__(16) float    g_b2i[SEG];              // binv + Winv@b2

// ---------------- helpers ----------------
__device__ __forceinline__ uint32_t f2h2(float lo, float hi) {
    uint32_t u;
    asm("cvt.rn.f16x2.f32 %0, %1, %2;" : "=r"(u) : "f"(hi), "f"(lo));
    return u;
}
__device__ __forceinline__ void cpasync16(uint32_t saddr, const void* gaddr) {
    asm volatile("cp.async.cg.shared.global [%0], [%1], 16;" :: "r"(saddr), "l"(gaddr));
}
#define CPASYNC_COMMIT() asm volatile("cp.async.commit_group;")
#define CPASYNC_WAIT0()  asm volatile("cp.async.wait_group 0;")

#define MMA_F16(C, A, b0v, b1v)                                                \
    asm volatile(                                                              \
        "mma.sync.aligned.m16n8k16.row.col.f32.f16.f16.f32 "                   \
        "{%0,%1,%2,%3},{%4,%5,%6,%7},{%8,%9},{%0,%1,%2,%3};"                   \
        : "+f"((C)[0]), "+f"((C)[1]), "+f"((C)[2]), "+f"((C)[3])               \
        : "r"((A)[0]), "r"((A)[1]), "r"((A)[2]), "r"((A)[3]),                  \
          "r"(b0v), "r"(b1v))

// ---------------- prep kernels ----------------
// GEMM1-B pack: g_W1h[((w*8+ks)*32+l)*8 + nt*2+r] =
//   f16x2{ W1[j][k0], W1[j][k0+1] }, j = 32w+8nt+g, k0 = 16ks+2tg+8r
__global__ void prep_w1h(const float* __restrict__ W1) {
    int id = blockIdx.x * 256 + threadIdx.x;     // 16384
    int v  = id & 7;
    int l  = (id >> 3) & 31;
    int ks = (id >> 8) & 7;
    int w  = (id >> 11) & 7;
    int g = l >> 2, tg = l & 3, nt = v >> 1, r = v & 1;
    int j  = 32 * w + 8 * nt + g;
    int k0 = 16 * ks + 2 * tg + 8 * r;
    g_W1h[id] = f2h2(W1[j * NE + k0], W1[j * NE + k0 + 1]);
}

// W2T[h][s] = sum_e Winv[s][e]*W2[e][h];  b2i[s] = binv[s] + Winv[s]·b2
__global__ void prep_w2(const float* __restrict__ W2, const float* __restrict__ Winv,
                        const float* __restrict__ b2, const float* __restrict__ binv) {
    int s = blockIdx.x;        // 64
    int h = threadIdx.x;       // 256
    const float* wr = Winv + s * NE;
    float acc = 0.f;
    #pragma unroll 4
    for (int e = 0; e < NE; ++e) acc += wr[e] * W2[e * NH + h];
    g_W2T[h * SEG + s] = acc;
    if (h == 0) {
        float t = 0.f;
        for (int e = 0; e < NE; ++e) t += wr[e] * b2[e];
        g_b2i[s] = binv[s] + t;
    }
}

// GEMM2-B pack: g_W2h[(((kq*4+ksl)*2+sh)*32+l)*8 + nt2*2+r] =
//   f16x2{ W2T[k0][s], W2T[k0+1][s] }, k0 = 16*(4kq+ksl)+2tg+8r, s = 32sh+8nt2+g
__global__ void prep_w2h() {
    int id  = blockIdx.x * 256 + threadIdx.x;    // 8192
    int v   = id & 7;
    int l   = (id >> 3) & 31;
    int sh  = (id >> 8) & 1;
    int ksl = (id >> 9) & 3;
    int kq  = (id >> 11) & 3;
    int g = l >> 2, tg = l & 3, nt2 = v >> 1, r = v & 1;
    int k0 = 16 * (4 * kq + ksl) + 2 * tg + 8 * r;
    int s  = 32 * sh + 8 * nt2 + g;
    g_W2h[id] = f2h2(g_W2T[k0 * SEG + s], g_W2T[(k0 + 1) * SEG + s]);
}

// ---------------- main kernel ----------------
// smem float offsets (~107.5 KB -> 2 CTAs/SM)
#define OFF_E32  0        // 8192   pair fp32 enc (cp.async target, linear)
#define OFF_EH   8192     // 4352   2ch fp16 enc tiles [32 rows][68 words]
#define OFF_HA   12544    // 4224   hA fp16 [32 rows][132 words]
#define OFF_SEG  16768    // 8704   4 partial seg [32][68] fp32
#define OFF_SIG  25472    // 1058
#define OFF_B1   26530    // 256
#define OFF_B2   26786    // 64
#define OFF_WCV  26850    // 24
#define SMEM_FLOATS 26880
#define SMEM_BYTES  (SMEM_FLOATS * 4)

__device__ __forceinline__ float cinvf(int p) {
    return (p < 32 || p >= 1024) ? 1.0f : 0.5f;   // 1/overlap-count
}

__global__ __launch_bounds__(256, 2)
void decoder_main(const float* __restrict__ enc, const float* __restrict__ b1,
                  const float* __restrict__ Wconv, const float* __restrict__ bconv,
                  float* __restrict__ out) {
    extern __shared__ float sm[];
    const float4* e32f4 = (const float4*)(sm + OFF_E32);
    uint32_t*     ehW   = (uint32_t*)(sm + OFF_EH);
    uint32_t*     hAW   = (uint32_t*)(sm + OFF_HA);
    float*        segB  = sm + OFF_SEG;
    float*        sig   = sm + OFF_SIG;
    float*        b1s   = sm + OFF_B1;
    float*        b2s   = sm + OFF_B2;
    float*        wcv   = sm + OFF_WCV;
    const uint32_t smemBase = (uint32_t)__cvta_generic_to_shared(sm);

    const int tid = threadIdx.x;
    const int l   = tid & 31;
    const int w   = tid >> 5;       // warp 0..7
    const int g   = l >> 2;
    const int tg  = l & 3;
    const int b   = blockIdx.x;
    const int kq  = w >> 1;         // GEMM2 K-quarter
    const int sh  = w & 1;          // GEMM2 s-half

    b1s[tid] = b1[tid];
    if (tid < SEG) b2s[tid] = g_b2i[tid];
    if (tid < 24)  wcv[tid] = Wconv[tid];
    if (tid == 0) { sig[0] = 0.f; sig[1057] = 0.f; }

    float oa[5];
    #pragma unroll
    for (int i = 0; i < 5; ++i) oa[i] = 0.f;

    // conv tap accumulate for channel c (reads sig, writes oa regs only)
    auto conv_tap = [&](int c) {
        float w0c = wcv[c * 3 + 0];
        float w1c = wcv[c * 3 + 1];
        float w2c = wcv[c * 3 + 2];
        #pragma unroll
        for (int i = 0; i < 5; ++i) {
            int p = tid + 256 * i;
            if (p < SIG)
                oa[i] += w0c * sig[p] + w1c * sig[p + 1] + w2c * sig[p + 2];
        }
    };

    // ---- prologue: cp.async pair 0 (fp32, linear) ----
    {
        const float* src = enc + (size_t)b * NC * (NT * NE);
        #pragma unroll
        for (int i = 0; i < 8; ++i) {
            int fi = tid + 256 * i;
            cpasync16(smemBase + (uint32_t)(OFF_E32 * 4 + fi * 16), src + fi * 4);
        }
        CPASYNC_COMMIT();
    }

    for (int cp = 0; cp < 4; ++cp) {
        CPASYNC_WAIT0();
        __syncthreads();            // enc(pair cp) staged; sig(prev sub1) visible

        // ---- MERGED: convert fp32->fp16 tiles  +  deferred conv(ch 2cp-1) ----
        #pragma unroll
        for (int i = 0; i < 8; ++i) {
            int fi = tid + 256 * i;
            int ch = fi >> 10, rem = fi & 1023;
            int row = rem >> 5, kk = rem & 31;
            float4 v = e32f4[fi];
            uint2 u;
            u.x = f2h2(v.x, v.y);
            u.y = f2h2(v.z, v.w);
            *(uint2*)(ehW + ch * 2176 + row * 68 + 2 * kk) = u;
        }
        if (cp > 0) conv_tap(2 * cp - 1);
        __syncthreads();            // ehW ready; E32 consumed

        // ---- prefetch next pair into freed fp32 buffer ----
        if (cp < 3) {
            const float* src = enc + ((size_t)b * NC + 2 * (cp + 1)) * (NT * NE);
            #pragma unroll
            for (int i = 0; i < 8; ++i) {
                int fi = tid + 256 * i;
                cpasync16(smemBase + (uint32_t)(OFF_E32 * 4 + fi * 16), src + fi * 4);
            }
            CPASYNC_COMMIT();
        }

        // ---- GEMM1 (fp16): both channels, B depth-2 prefetched from L2 ----
        float c1[2][2][4][4];                       // [ch][mt][nt][4]
        #pragma unroll
        for (int nt = 0; nt < 4; ++nt) {
            float bb0 = b1s[32 * w + 8 * nt + 2 * tg];
            float bb1 = b1s[32 * w + 8 * nt + 2 * tg + 1];
            #pragma unroll
            for (int ch = 0; ch < 2; ++ch)
                #pragma unroll
                for (int mt = 0; mt < 2; ++mt) {
                    c1[ch][mt][nt][0] = bb0; c1[ch][mt][nt][1] = bb1;
                    c1[ch][mt][nt][2] = bb0; c1[ch][mt][nt][3] = bb1;
                }
        }
        {
            const uint4* W1g = (const uint4*)g_W1h;
            int bidx = w * 512 + l * 2;             // ((w*8+ks)*32+l)*2, ks=0
            uint4 Bq0[2], Bq1[2];
            Bq0[0] = __ldg(&W1g[bidx]);
            Bq1[0] = __ldg(&W1g[bidx + 1]);
            Bq0[1] = __ldg(&W1g[bidx + 64]);
            Bq1[1] = __ldg(&W1g[bidx + 64 + 1]);
            #pragma unroll
            for (int ks = 0; ks < 8; ++ks) {
                uint4 b0v = Bq0[ks & 1];
                uint4 b1v = Bq1[ks & 1];
                if (ks < 6) {
                    Bq0[ks & 1] = __ldg(&W1g[bidx + 64 * (ks + 2)]);
                    Bq1[ks & 1] = __ldg(&W1g[bidx + 64 * (ks + 2) + 1]);
                }
                #pragma unroll
                for (int ch = 0; ch < 2; ++ch) {
                    const uint32_t* eW = ehW + ch * 2176;
                    #pragma unroll
                    for (int mt = 0; mt < 2; ++mt) {
                        uint32_t a[4];
                        int r0 = (16 * mt + g) * 68;
                        int k0 = 8 * ks + tg;
                        a[0] = eW[r0 + k0];
                        a[1] = eW[r0 + 8 * 68 + k0];
                        a[2] = eW[r0 + k0 + 4];
                        a[3] = eW[r0 + 8 * 68 + k0 + 4];
                        MMA_F16(c1[ch][mt][0], a, b0v.x, b0v.y);
                        MMA_F16(c1[ch][mt][1], a, b0v.z, b0v.w);
                        MMA_F16(c1[ch][mt][2], a, b1v.x, b1v.y);
                        MMA_F16(c1[ch][mt][3], a, b1v.z, b1v.w);
                    }
                }
            }
        }

        #pragma unroll
        for (int sub = 0; sub < 2; ++sub) {
            // ---- MERGED: epilogue(sub)  +  conv(sub-1) for sub==1 ----
            {
                int jp = 16 * w + tg;               // + 4*nt below
                #pragma unroll
                for (int mt = 0; mt < 2; ++mt)
                    #pragma unroll
                    for (int nt = 0; nt < 4; ++nt) {
                        float r0a = fmaxf(c1[sub][mt][nt][0], 0.f);
                        float r0b = fmaxf(c1[sub][mt][nt][1], 0.f);
                        float r1a = fmaxf(c1[sub][mt][nt][2], 0.f);
                        float r1b = fmaxf(c1[sub][mt][nt][3], 0.f);
                        hAW[(16 * mt + g) * 132 + jp + 4 * nt]     = f2h2(r0a, r0b);
                        hAW[(16 * mt + g + 8) * 132 + jp + 4 * nt] = f2h2(r1a, r1b);
                    }
                if (sub == 1) conv_tap(2 * cp);     // sig(sub0) stable; disjoint smem
            }
            __syncthreads();

            // ---- GEMM2 (fp16): B fully prefetched (MLP=8) + seg store ----
            float c2[2][4][4];                      // [mt][nt2][4]
            {
                const uint4* W2g = (const uint4*)g_W2h;
                int b2idx = (((kq * 4) * 2 + sh) * 32 + l) * 2;
                uint4 Bf0[4], Bf1[4];
                #pragma unroll
                for (int ksl = 0; ksl < 4; ++ksl) {
                    Bf0[ksl] = __ldg(&W2g[b2idx + 128 * ksl]);
                    Bf1[ksl] = __ldg(&W2g[b2idx + 128 * ksl + 1]);
                }
                #pragma unroll
                for (int nt2 = 0; nt2 < 4; ++nt2) {
                    float bb0 = (kq == 0) ? b2s[32 * sh + 8 * nt2 + 2 * tg] : 0.f;
                    float bb1 = (kq == 0) ? b2s[32 * sh + 8 * nt2 + 2 * tg + 1] : 0.f;
                    #pragma unroll
                    for (int mt = 0; mt < 2; ++mt) {
                        c2[mt][nt2][0] = bb0; c2[mt][nt2][1] = bb1;
                        c2[mt][nt2][2] = bb0; c2[mt][nt2][3] = bb1;
                    }
                }
                #pragma unroll
                for (int ksl = 0; ksl < 4; ++ksl) {
                    int k0 = 8 * (4 * kq + ksl) + tg;
                    #pragma unroll
                    for (int mt = 0; mt < 2; ++mt) {
                        uint32_t a[4];
                        int r0 = (16 * mt + g) * 132;
                        a[0] = hAW[r0 + k0];
                        a[1] = hAW[r0 + 8 * 132 + k0];
                        a[2] = hAW[r0 + k0 + 4];
                        a[3] = hAW[r0 + 8 * 132 + k0 + 4];
                        MMA_F16(c2[mt][0], a, Bf0[ksl].x, Bf0[ksl].y);
                        MMA_F16(c2[mt][1], a, Bf0[ksl].z, Bf0[ksl].w);
                        MMA_F16(c2[mt][2], a, Bf1[ksl].x, Bf1[ksl].y);
                        MMA_F16(c2[mt][3], a, Bf1[ksl].z, Bf1[ksl].w);
                    }
                }
                float* sp = segB + kq * 2176;
                #pragma unroll
                for (int mt = 0; mt < 2; ++mt)
                    #pragma unroll
                    for (int nt2 = 0; nt2 < 4; ++nt2) {
                        int s0 = 32 * sh + 8 * nt2 + 2 * tg;
                        float2 v0 = make_float2(c2[mt][nt2][0], c2[mt][nt2][1]);
                        float2 v1 = make_float2(c2[mt][nt2][2], c2[mt][nt2][3]);
                        *(float2*)&sp[(16 * mt + g) * 68 + s0]     = v0;
                        *(float2*)&sp[(16 * mt + g + 8) * 68 + s0] = v1;
                    }
            }
            __syncthreads();

            // ---- overlap-add + normalize -> sig ----
            for (int p = tid; p < SIG; p += 256) {
                int t = p >> 5, s = p & 31;
                float v = 0.f;
                #pragma unroll
                for (int q = 0; q < 4; ++q) {
                    const float* sp = segB + q * 2176;
                    if (t < 32) v += sp[t * 68 + s];
                    if (t > 0)  v += sp[(t - 1) * 68 + s + 32];
                }
                sig[1 + p] = v * cinvf(p);
            }
            if (sub == 0) __syncthreads();  // sub1 uses loop-top / post-epilogue sync
        }
        __syncthreads();                    // sig(sub1) visible to next pair's conv
    }

    // ---- final deferred conv (channel 7) + output ----
    conv_tap(7);
    float bc = bconv[0];
    #pragma unroll
    for (int i = 0; i < 5; ++i) {
        int p = tid + 256 * i;
        if (p < SIG) out[(size_t)b * SIG + p] = oa[i] + bc;
    }
}

// ---------------- launch ----------------
extern "C" void kernel_launch(void* const* d_in, const int* in_sizes, int n_in,
                              void* d_out, int out_size) {
    (void)in_sizes; (void)n_in; (void)out_size;
    const float* enc   = (const float*)d_in[0];
    const float* W1    = (const float*)d_in[1];
    const float* b1    = (const float*)d_in[2];
    const float* W2    = (const float*)d_in[3];
    const float* b2    = (const float*)d_in[4];
    const float* Winv  = (const float*)d_in[5];
    const float* binv  = (const float*)d_in[6];
    const float* Wconv = (const float*)d_in[7];
    const float* bconv = (const float*)d_in[8];
    float* out = (float*)d_out;

    cudaFuncSetAttribute(decoder_main, cudaFuncAttributeMaxDynamicSharedMemorySize,
                         SMEM_BYTES);

    prep_w1h<<<64, 256>>>(W1);
    prep_w2<<<64, 256>>>(W2, Winv, b2, binv);
    prep_w2h<<<32, 256>>>();
    decoder_main<<<NB, 256, SMEM_BYTES>>>(enc, b1, Wconv, bconv, out);
}

// round 17
// speedup vs baseline: 1.6554x; 1.0161x over previous
#include <cuda_runtime.h>
#include <cstdint>
#include <cstddef>

#define NB   1024
#define NC   8
#define NT   32
#define NE   128
#define NH   256
#define SEG  64
#define SIG  1056

// ---------------- device scratch (static; no allocations) ----------------
__device__ __align__(16) uint32_t g_W1h[8 * 8 * 32 * 8];     // 16384 f16x2 words, GEMM1-B pack
__device__ __align__(16) uint32_t g_W2h[4 * 4 * 2 * 32 * 8]; // 8192 f16x2 words, GEMM2-B pack
__device__ __align__(16) float    g_b2i[SEG];                // binv + Winv@b2

// ---------------- helpers ----------------
__device__ __forceinline__ uint32_t f2h2(float lo, float hi) {
    uint32_t u;
    asm("cvt.rn.f16x2.f32 %0, %1, %2;" : "=r"(u) : "f"(hi), "f"(lo));
    return u;
}
__device__ __forceinline__ void cpasync16(uint32_t saddr, const void* gaddr) {
    asm volatile("cp.async.cg.shared.global [%0], [%1], 16;" :: "r"(saddr), "l"(gaddr));
}
#define CPASYNC_COMMIT() asm volatile("cp.async.commit_group;")
#define CPASYNC_WAIT0()  asm volatile("cp.async.wait_group 0;")

#define MMA_F16(C, A, b0v, b1v)                                                \
    asm volatile(                                                              \
        "mma.sync.aligned.m16n8k16.row.col.f32.f16.f16.f32 "                   \
        "{%0,%1,%2,%3},{%4,%5,%6,%7},{%8,%9},{%0,%1,%2,%3};"                   \
        : "+f"((C)[0]), "+f"((C)[1]), "+f"((C)[2]), "+f"((C)[3])               \
        : "r"((A)[0]), "r"((A)[1]), "r"((A)[2]), "r"((A)[3]),                  \
          "r"(b0v), "r"(b1v))

// ---------------- fused prep kernel ----------------
// Blocks 0..63  (s = blockIdx):   W2T column s -> smem, b2i[s], pack g_W2h entries for s.
// Blocks 64..127:                 W1 -> GEMM1-B frag pack (same mapping as before).
//
// GEMM1-B pack: g_W1h[((w*8+ks)*32+l)*8 + nt*2+r] =
//   f16x2{ W1[j][k0], W1[j][k0+1] }, j = 32w+8nt+g, k0 = 16ks+2tg+8r
// GEMM2-B pack: g_W2h[(((kq*4+ksl)*2+sh)*32+l)*8 + nt2*2+r] =
//   f16x2{ W2T[k0][s], W2T[k0+1][s] }, k0 = 16*(4kq+ksl)+2tg+8r, s = 32sh+8nt2+g, l = 4g+tg
__global__ void prep_fused(const float* __restrict__ W1, const float* __restrict__ W2,
                           const float* __restrict__ Winv, const float* __restrict__ b2,
                           const float* __restrict__ binv) {
    int tid = threadIdx.x;
    if (blockIdx.x < 64) {
        __shared__ float col[NH];
        int s = blockIdx.x;
        const float* wr = Winv + s * NE;
        {   // W2T[h][s] = sum_e Winv[s][e] * W2[e][h]  (same order as before)
            int h = tid;
            float acc = 0.f;
            #pragma unroll 4
            for (int e = 0; e < NE; ++e) acc += wr[e] * W2[e * NH + h];
            col[h] = acc;
        }
        if (tid == 0) {
            float t = 0.f;
            for (int e = 0; e < NE; ++e) t += wr[e] * b2[e];
            g_b2i[s] = binv[s] + t;
        }
        __syncthreads();
        if (tid < 128) {
            int r   = tid & 1;
            int tg  = (tid >> 1) & 3;
            int ksl = (tid >> 3) & 3;
            int kq  = tid >> 5;
            int k0  = 16 * (4 * kq + ksl) + 2 * tg + 8 * r;
            int sh  = s >> 5;
            int nt2 = (s >> 3) & 3;
            int g   = s & 7;
            int l   = 4 * g + tg;
            g_W2h[(((kq * 4 + ksl) * 2 + sh) * 32 + l) * 8 + nt2 * 2 + r] =
                f2h2(col[k0], col[k0 + 1]);
        }
    } else {
        int id = (blockIdx.x - 64) * 256 + tid;      // 16384
        int v  = id & 7;
        int l  = (id >> 3) & 31;
        int ks = (id >> 8) & 7;
        int w  = (id >> 11) & 7;
        int g = l >> 2, tg = l & 3, nt = v >> 1, r = v & 1;
        int j  = 32 * w + 8 * nt + g;
        int k0 = 16 * ks + 2 * tg + 8 * r;
        g_W1h[id] = f2h2(W1[j * NE + k0], W1[j * NE + k0 + 1]);
    }
}

// ---------------- main kernel (byte-identical to round 16) ----------------
// smem float offsets (~107.5 KB -> 2 CTAs/SM)
#define OFF_E32  0        // 8192   pair fp32 enc (cp.async target, linear)
#define OFF_EH   8192     // 4352   2ch fp16 enc tiles [32 rows][68 words]
#define OFF_HA   12544    // 4224   hA fp16 [32 rows][132 words]
#define OFF_SEG  16768    // 8704   4 partial seg [32][68] fp32
#define OFF_SIG  25472    // 1058
#define OFF_B1   26530    // 256
#define OFF_B2   26786    // 64
#define OFF_WCV  26850    // 24
#define SMEM_FLOATS 26880
#define SMEM_BYTES  (SMEM_FLOATS * 4)

__device__ __forceinline__ float cinvf(int p) {
    return (p < 32 || p >= 1024) ? 1.0f : 0.5f;   // 1/overlap-count
}

__global__ __launch_bounds__(256, 2)
void decoder_main(const float* __restrict__ enc, const float* __restrict__ b1,
                  const float* __restrict__ Wconv, const float* __restrict__ bconv,
                  float* __restrict__ out) {
    extern __shared__ float sm[];
    const float4* e32f4 = (const float4*)(sm + OFF_E32);
    uint32_t*     ehW   = (uint32_t*)(sm + OFF_EH);
    uint32_t*     hAW   = (uint32_t*)(sm + OFF_HA);
    float*        segB  = sm + OFF_SEG;
    float*        sig   = sm + OFF_SIG;
    float*        b1s   = sm + OFF_B1;
    float*        b2s   = sm + OFF_B2;
    float*        wcv   = sm + OFF_WCV;
    const uint32_t smemBase = (uint32_t)__cvta_generic_to_shared(sm);

    const int tid = threadIdx.x;
    const int l   = tid & 31;
    const int w   = tid >> 5;       // warp 0..7
    const int g   = l >> 2;
    const int tg  = l & 3;
    const int b   = blockIdx.x;
    const int kq  = w >> 1;         // GEMM2 K-quarter
    const int sh  = w & 1;          // GEMM2 s-half

    b1s[tid] = b1[tid];
    if (tid < SEG) b2s[tid] = g_b2i[tid];
    if (tid < 24)  wcv[tid] = Wconv[tid];
    if (tid == 0) { sig[0] = 0.f; sig[1057] = 0.f; }

    float oa[5];
    #pragma unroll
    for (int i = 0; i < 5; ++i) oa[i] = 0.f;

    // conv tap accumulate for channel c (reads sig, writes oa regs only)
    auto conv_tap = [&](int c) {
        float w0c = wcv[c * 3 + 0];
        float w1c = wcv[c * 3 + 1];
        float w2c = wcv[c * 3 + 2];
        #pragma unroll
        for (int i = 0; i < 5; ++i) {
            int p = tid + 256 * i;
            if (p < SIG)
                oa[i] += w0c * sig[p] + w1c * sig[p + 1] + w2c * sig[p + 2];
        }
    };

    // ---- prologue: cp.async pair 0 (fp32, linear) ----
    {
        const float* src = enc + (size_t)b * NC * (NT * NE);
        #pragma unroll
        for (int i = 0; i < 8; ++i) {
            int fi = tid + 256 * i;
            cpasync16(smemBase + (uint32_t)(OFF_E32 * 4 + fi * 16), src + fi * 4);
        }
        CPASYNC_COMMIT();
    }

    for (int cp = 0; cp < 4; ++cp) {
        CPASYNC_WAIT0();
        __syncthreads();            // enc(pair cp) staged; sig(prev sub1) visible

        // ---- MERGED: convert fp32->fp16 tiles  +  deferred conv(ch 2cp-1) ----
        #pragma unroll
        for (int i = 0; i < 8; ++i) {
            int fi = tid + 256 * i;
            int ch = fi >> 10, rem = fi & 1023;
            int row = rem >> 5, kk = rem & 31;
            float4 v = e32f4[fi];
            uint2 u;
            u.x = f2h2(v.x, v.y);
            u.y = f2h2(v.z, v.w);
            *(uint2*)(ehW + ch * 2176 + row * 68 + 2 * kk) = u;
        }
        if (cp > 0) conv_tap(2 * cp - 1);
        __syncthreads();            // ehW ready; E32 consumed

        // ---- prefetch next pair into freed fp32 buffer ----
        if (cp < 3) {
            const float* src = enc + ((size_t)b * NC + 2 * (cp + 1)) * (NT * NE);
            #pragma unroll
            for (int i = 0; i < 8; ++i) {
                int fi = tid + 256 * i;
                cpasync16(smemBase + (uint32_t)(OFF_E32 * 4 + fi * 16), src + fi * 4);
            }
            CPASYNC_COMMIT();
        }

        // ---- GEMM1 (fp16): both channels, B depth-2 prefetched from L2 ----
        float c1[2][2][4][4];                       // [ch][mt][nt][4]
        #pragma unroll
        for (int nt = 0; nt < 4; ++nt) {
            float bb0 = b1s[32 * w + 8 * nt + 2 * tg];
            float bb1 = b1s[32 * w + 8 * nt + 2 * tg + 1];
            #pragma unroll
            for (int ch = 0; ch < 2; ++ch)
                #pragma unroll
                for (int mt = 0; mt < 2; ++mt) {
                    c1[ch][mt][nt][0] = bb0; c1[ch][mt][nt][1] = bb1;
                    c1[ch][mt][nt][2] = bb0; c1[ch][mt][nt][3] = bb1;
                }
        }
        {
            const uint4* W1g = (const uint4*)g_W1h;
            int bidx = w * 512 + l * 2;             // ((w*8+ks)*32+l)*2, ks=0
            uint4 Bq0[2], Bq1[2];
            Bq0[0] = __ldg(&W1g[bidx]);
            Bq1[0] = __ldg(&W1g[bidx + 1]);
            Bq0[1] = __ldg(&W1g[bidx + 64]);
            Bq1[1] = __ldg(&W1g[bidx + 64 + 1]);
            #pragma unroll
            for (int ks = 0; ks < 8; ++ks) {
                uint4 b0v = Bq0[ks & 1];
                uint4 b1v = Bq1[ks & 1];
                if (ks < 6) {
                    Bq0[ks & 1] = __ldg(&W1g[bidx + 64 * (ks + 2)]);
                    Bq1[ks & 1] = __ldg(&W1g[bidx + 64 * (ks + 2) + 1]);
                }
                #pragma unroll
                for (int ch = 0; ch < 2; ++ch) {
                    const uint32_t* eW = ehW + ch * 2176;
                    #pragma unroll
                    for (int mt = 0; mt < 2; ++mt) {
                        uint32_t a[4];
                        int r0 = (16 * mt + g) * 68;
                        int k0 = 8 * ks + tg;
                        a[0] = eW[r0 + k0];
                        a[1] = eW[r0 + 8 * 68 + k0];
                        a[2] = eW[r0 + k0 + 4];
                        a[3] = eW[r0 + 8 * 68 + k0 + 4];
                        MMA_F16(c1[ch][mt][0], a, b0v.x, b0v.y);
                        MMA_F16(c1[ch][mt][1], a, b0v.z, b0v.w);
                        MMA_F16(c1[ch][mt][2], a, b1v.x, b1v.y);
                        MMA_F16(c1[ch][mt][3], a, b1v.z, b1v.w);
                    }
                }
            }
        }

        #pragma unroll
        for (int sub = 0; sub < 2; ++sub) {
            // ---- MERGED: epilogue(sub)  +  conv(sub-1) for sub==1 ----
            {
                int jp = 16 * w + tg;               // + 4*nt below
                #pragma unroll
                for (int mt = 0; mt < 2; ++mt)
                    #pragma unroll
                    for (int nt = 0; nt < 4; ++nt) {
                        float r0a = fmaxf(c1[sub][mt][nt][0], 0.f);
                        float r0b = fmaxf(c1[sub][mt][nt][1], 0.f);
                        float r1a = fmaxf(c1[sub][mt][nt][2], 0.f);
                        float r1b = fmaxf(c1[sub][mt][nt][3], 0.f);
                        hAW[(16 * mt + g) * 132 + jp + 4 * nt]     = f2h2(r0a, r0b);
                        hAW[(16 * mt + g + 8) * 132 + jp + 4 * nt] = f2h2(r1a, r1b);
                    }
                if (sub == 1) conv_tap(2 * cp);     // sig(sub0) stable; disjoint smem
            }
            __syncthreads();

            // ---- GEMM2 (fp16): B fully prefetched (MLP=8) + seg store ----
            float c2[2][4][4];                      // [mt][nt2][4]
            {
                const uint4* W2g = (const uint4*)g_W2h;
                int b2idx = (((kq * 4) * 2 + sh) * 32 + l) * 2;
                uint4 Bf0[4], Bf1[4];
                #pragma unroll
                for (int ksl = 0; ksl < 4; ++ksl) {
                    Bf0[ksl] = __ldg(&W2g[b2idx + 128 * ksl]);
                    Bf1[ksl] = __ldg(&W2g[b2idx + 128 * ksl + 1]);
                }
                #pragma unroll
                for (int nt2 = 0; nt2 < 4; ++nt2) {
                    float bb0 = (kq == 0) ? b2s[32 * sh + 8 * nt2 + 2 * tg] : 0.f;
                    float bb1 = (kq == 0) ? b2s[32 * sh + 8 * nt2 + 2 * tg + 1] : 0.f;
                    #pragma unroll
                    for (int mt = 0; mt < 2; ++mt) {
                        c2[mt][nt2][0] = bb0; c2[mt][nt2][1] = bb1;
                        c2[mt][nt2][2] = bb0; c2[mt][nt2][3] = bb1;
                    }
                }
                #pragma unroll
                for (int ksl = 0; ksl < 4; ++ksl) {
                    int k0 = 8 * (4 * kq + ksl) + tg;
                    #pragma unroll
                    for (int mt = 0; mt < 2; ++mt) {
                        uint32_t a[4];
                        int r0 = (16 * mt + g) * 132;
                        a[0] = hAW[r0 + k0];
                        a[1] = hAW[r0 + 8 * 132 + k0];
                        a[2] = hAW[r0 + k0 + 4];
                        a[3] = hAW[r0 + 8 * 132 + k0 + 4];
                        MMA_F16(c2[mt][0], a, Bf0[ksl].x, Bf0[ksl].y);
                        MMA_F16(c2[mt][1], a, Bf0[ksl].z, Bf0[ksl].w);
                        MMA_F16(c2[mt][2], a, Bf1[ksl].x, Bf1[ksl].y);
                        MMA_F16(c2[mt][3], a, Bf1[ksl].z, Bf1[ksl].w);
                    }
                }
                float* sp = segB + kq * 2176;
                #pragma unroll
                for (int mt = 0; mt < 2; ++mt)
                    #pragma unroll
                    for (int nt2 = 0; nt2 < 4; ++nt2) {
                        int s0 = 32 * sh + 8 * nt2 + 2 * tg;
                        float2 v0 = make_float2(c2[mt][nt2][0], c2[mt][nt2][1]);
                        float2 v1 = make_float2(c2[mt][nt2][2], c2[mt][nt2][3]);
                        *(float2*)&sp[(16 * mt + g) * 68 + s0]     = v0;
                        *(float2*)&sp[(16 * mt + g + 8) * 68 + s0] = v1;
                    }
            }
            __syncthreads();

            // ---- overlap-add + normalize -> sig ----
            for (int p = tid; p < SIG; p += 256) {
                int t = p >> 5, s = p & 31;
                float v = 0.f;
                #pragma unroll
                for (int q = 0; q < 4; ++q) {
                    const float* sp = segB + q * 2176;
                    if (t < 32) v += sp[t * 68 + s];
                    if (t > 0)  v += sp[(t - 1) * 68 + s + 32];
                }
                sig[1 + p] = v * cinvf(p);
            }
            if (sub == 0) __syncthreads();  // sub1 uses loop-top / post-epilogue sync
        }
        __syncthreads();                    // sig(sub1) visible to next pair's conv
    }

    // ---- final deferred conv (channel 7) + output ----
    conv_tap(7);
    float bc = bconv[0];
    #pragma unroll
    for (int i = 0; i < 5; ++i) {
        int p = tid + 256 * i;
        if (p < SIG) out[(size_t)b * SIG + p] = oa[i] + bc;
    }
}

// ---------------- launch ----------------
extern "C" void kernel_launch(void* const* d_in, const int* in_sizes, int n_in,
                              void* d_out, int out_size) {
    (void)in_sizes; (void)n_in; (void)out_size;
    const float* enc   = (const float*)d_in[0];
    const float* W1    = (const float*)d_in[1];
    const float* b1    = (const float*)d_in[2];
    const float* W2    = (const float*)d_in[3];
    const float* b2    = (const float*)d_in[4];
    const float* Winv  = (const float*)d_in[5];
    const float* binv  = (const float*)d_in[6];
    const float* Wconv = (const float*)d_in[7];
    const float* bconv = (const float*)d_in[8];
    float* out = (float*)d_out;

    cudaFuncSetAttribute(decoder_main, cudaFuncAttributeMaxDynamicSharedMemorySize,
                         SMEM_BYTES);

    prep_fused<<<128, 256>>>(W1, W2, Winv, b2, binv);
    decoder_main<<<NB, 256, SMEM_BYTES>>>(enc, b1, Wconv, bconv, out);
}